// round 12
// baseline (speedup 1.0000x reference)
#include <cuda_runtime.h>
#include <math.h>
#include <stdint.h>

// ---------------------------------------------------------------------------
// RandomProjection: out[b,o] = mean_s( cos(x[b,s,:], p[o,:]) )
//   kernel 1: m = mean_s(x/||x||) -> tf32 hi/lo split (g_mhi/g_mlo);
//             p-norms -> g_rpn; zero(out)
//   kernel 2: 3xTF32 tensor-core GEMM (mma.sync.m16n8k8), transposed smem,
//             red.add.v2.f32 epilogue
// ---------------------------------------------------------------------------

#define B_     32
#define S_     512
#define D_     768
#define O_     2048
#define EPS_   1e-8f

#define KSPLIT 24
#define KB     32            // k floats per gemm block
#define OTILE  128           // o rows per gemm block
#define NOT_   (O_ / OTILE)  // 16 o-tiles
#define PMB    36            // msm pitch [k][b]
#define PPO    132           // psm pitch [k][o]

__device__ float g_part[4 * B_ * D_];    // x partials (race-free)
__device__ float g_mhi[B_ * D_];         // tf32 hi of combined mean
__device__ float g_mlo[B_ * D_];         // tf32 lo
__device__ float g_rpn[O_];              // 1/max(||p_o||,eps)
__device__ int   g_ticket[B_];           // kernel1 tickets (zero-init, self-reset)

// ---- tf32 helpers -----------------------------------------------------------
__device__ __forceinline__ uint32_t tf32_rd(float x) {
    uint32_t r; asm("cvt.rna.tf32.f32 %0, %1;" : "=r"(r) : "f"(x)); return r;
}
__device__ __forceinline__ void tf32_split(float x, float& hi, float& lo) {
    const uint32_t h = tf32_rd(x);
    hi = __uint_as_float(h);
    lo = __uint_as_float(tf32_rd(x - hi));
}

// ---- mma.sync m16n8k8 tf32 --------------------------------------------------
__device__ __forceinline__ void mma_tf32(float* d, const uint32_t* a,
                                         const uint32_t* b) {
    asm volatile(
        "mma.sync.aligned.m16n8k8.row.col.f32.tf32.tf32.f32 "
        "{%0,%1,%2,%3}, {%4,%5,%6,%7}, {%8,%9}, {%0,%1,%2,%3};"
        : "+f"(d[0]), "+f"(d[1]), "+f"(d[2]), "+f"(d[3])
        : "r"(a[0]), "r"(a[1]), "r"(a[2]), "r"(a[3]), "r"(b[0]), "r"(b[1]));
}

// ---------------------------------------------------------------------------
// Kernel 1: blocks 0..127: x normalize+reduce; ticket combine -> hi/lo split.
//           blocks 128..143: p-norms (128 rows each) + zero out-slice.
// ---------------------------------------------------------------------------
__global__ void __launch_bounds__(512, 1)
reduce_x_kernel(const float* __restrict__ x, const float* __restrict__ p,
                float* __restrict__ out) {
    const int warp = threadIdx.x >> 5;
    const int lane = threadIdx.x & 31;

    if (blockIdx.x >= 128) {
        const int blk = blockIdx.x - 128;      // 0..15
        {
            float4* o4 = reinterpret_cast<float4*>(out) + blk * 1024;
            o4[threadIdx.x]       = make_float4(0.f, 0.f, 0.f, 0.f);
            o4[threadIdx.x + 512] = make_float4(0.f, 0.f, 0.f, 0.f);
        }
        const int row0 = blk * 128 + warp * 8;
        #pragma unroll 1
        for (int r = 0; r < 8; r++) {
            const int o = row0 + r;
            const float4* prow = reinterpret_cast<const float4*>(p + (size_t)o * D_);
            float ss = 0.f;
            #pragma unroll
            for (int c = 0; c < 6; c++) {
                const float4 v = prow[lane + 32 * c];
                ss += v.x * v.x + v.y * v.y + v.z * v.z + v.w * v.w;
            }
            #pragma unroll
            for (int off = 16; off > 0; off >>= 1)
                ss += __shfl_xor_sync(0xFFFFFFFFu, ss, off);
            if (lane == 0) g_rpn[o] = 1.0f / fmaxf(sqrtf(ss), EPS_);
        }
        return;
    }

    __shared__ float4 sm[16 * 192];
    __shared__ int is_last;

    const int q = blockIdx.x & 3;
    const int b = blockIdx.x >> 2;

    const float4* base = reinterpret_cast<const float4*>(
        x + ((size_t)b * S_ + (size_t)q * 128 + (size_t)warp * 8) * D_);

    const float inv_S = 1.0f / (float)S_;

    float4 acc[6];
    #pragma unroll
    for (int c = 0; c < 6; c++) acc[c] = make_float4(0.f, 0.f, 0.f, 0.f);

    float4 v[6];
    #pragma unroll
    for (int c = 0; c < 6; c++) v[c] = base[lane + 32 * c];

    #pragma unroll
    for (int r = 0; r < 8; r++) {
        float4 vn[6];
        if (r < 7) {
            #pragma unroll
            for (int c = 0; c < 6; c++)
                vn[c] = base[(r + 1) * 192 + lane + 32 * c];
        }
        float ss = 0.f;
        #pragma unroll
        for (int c = 0; c < 6; c++)
            ss += v[c].x * v[c].x + v[c].y * v[c].y
                + v[c].z * v[c].z + v[c].w * v[c].w;
        #pragma unroll
        for (int off = 16; off > 0; off >>= 1)
            ss += __shfl_xor_sync(0xFFFFFFFFu, ss, off);

        const float scale = inv_S / fmaxf(sqrtf(ss), EPS_);
        #pragma unroll
        for (int c = 0; c < 6; c++) {
            acc[c].x += v[c].x * scale;
            acc[c].y += v[c].y * scale;
            acc[c].z += v[c].z * scale;
            acc[c].w += v[c].w * scale;
        }
        if (r < 7) {
            #pragma unroll
            for (int c = 0; c < 6; c++) v[c] = vn[c];
        }
    }

    #pragma unroll
    for (int c = 0; c < 6; c++)
        sm[warp * 192 + lane + 32 * c] = acc[c];
    __syncthreads();

    if (threadIdx.x < 192) {
        float4 s = sm[threadIdx.x];
        #pragma unroll
        for (int w = 1; w < 16; w++) {
            const float4 t = sm[w * 192 + threadIdx.x];
            s.x += t.x; s.y += t.y; s.z += t.z; s.w += t.w;
        }
        reinterpret_cast<float4*>(g_part)[((q * B_ + b) * 192) + threadIdx.x] = s;
    }

    __threadfence();
    __syncthreads();
    if (threadIdx.x == 0)
        is_last = (atomicAdd(&g_ticket[b], 1) == 3) ? 1 : 0;
    __syncthreads();

    if (is_last) {
        __threadfence();
        if (threadIdx.x < 192) {
            const float4* gp = reinterpret_cast<const float4*>(g_part);
            float4 a  = gp[(0 * B_ + b) * 192 + threadIdx.x];
            const float4 b4 = gp[(1 * B_ + b) * 192 + threadIdx.x];
            const float4 c4 = gp[(2 * B_ + b) * 192 + threadIdx.x];
            const float4 d4 = gp[(3 * B_ + b) * 192 + threadIdx.x];
            a.x += b4.x + c4.x + d4.x;
            a.y += b4.y + c4.y + d4.y;
            a.z += b4.z + c4.z + d4.z;
            a.w += b4.w + c4.w + d4.w;
            float4 h, l;
            tf32_split(a.x, h.x, l.x);
            tf32_split(a.y, h.y, l.y);
            tf32_split(a.z, h.z, l.z);
            tf32_split(a.w, h.w, l.w);
            reinterpret_cast<float4*>(g_mhi)[b * 192 + threadIdx.x] = h;
            reinterpret_cast<float4*>(g_mlo)[b * 192 + threadIdx.x] = l;
        }
        if (threadIdx.x == 0) g_ticket[b] = 0;
    }
}

// ---------------------------------------------------------------------------
// Kernel 2: 3xTF32 tensor-core GEMM.
// Grid: 384 = 16 o-tiles x 24 k-splits. Block: 256 threads (8 warps), 43 KB.
// Warp: M=32 (full B), N=16 (warp*16 within 128-o tile), KB=32 per block.
// mma m16n8k8: per k8-step: A hi/lo frags (2 m-tiles), B hi/lo (2 n-tiles),
// 12 MMAs (AhBh, AhBl, AlBh). Epilogue: red.global.add.v2.f32 x8.
// ---------------------------------------------------------------------------
__global__ void __launch_bounds__(256, 4)
gemm_kernel(const float* __restrict__ p, float* __restrict__ out) {
    __shared__ float mh[KB * PMB];     // [k][b] tf32-hi of m
    __shared__ float ml[KB * PMB];     // [k][b] tf32-lo
    __shared__ float ph[KB * PPO];     // [k][o] tf32-hi of p*rpn
    __shared__ float pl[KB * PPO];     // [k][o] tf32-lo

    const int kq  = blockIdx.x % KSPLIT;
    const int ot  = blockIdx.x / KSPLIT;    // 0..15
    const int tid = threadIdx.x;
    const int k0  = kq * KB;

    // stage m hi/lo transposed -> [k][b]  (256 threads: b = tid>>3, kc = tid&7)
    {
        const int b  = tid >> 3;
        const int kc = tid & 7;
        const float4 vh = *reinterpret_cast<const float4*>(
            g_mhi + (size_t)b * D_ + k0 + kc * 4);
        const float4 vl = *reinterpret_cast<const float4*>(
            g_mlo + (size_t)b * D_ + k0 + kc * 4);
        mh[(kc * 4 + 0) * PMB + b] = vh.x;  ml[(kc * 4 + 0) * PMB + b] = vl.x;
        mh[(kc * 4 + 1) * PMB + b] = vh.y;  ml[(kc * 4 + 1) * PMB + b] = vl.y;
        mh[(kc * 4 + 2) * PMB + b] = vh.z;  ml[(kc * 4 + 2) * PMB + b] = vl.z;
        mh[(kc * 4 + 3) * PMB + b] = vh.w;  ml[(kc * 4 + 3) * PMB + b] = vl.w;
    }
    // stage p*rpn hi/lo transposed -> [k][o]
    #pragma unroll
    for (int t2 = 0; t2 < 4; t2++) {
        const int i  = tid + t2 * 256;       // 0..1023
        const int o  = i >> 3;               // 0..127
        const int kc = i & 7;                // 0..7
        const float4 v = *reinterpret_cast<const float4*>(
            p + (size_t)(ot * OTILE + o) * D_ + k0 + kc * 4);
        const float rp = g_rpn[ot * OTILE + o];
        float hi, lo;
        tf32_split(v.x * rp, hi, lo);
        ph[(kc * 4 + 0) * PPO + o] = hi;  pl[(kc * 4 + 0) * PPO + o] = lo;
        tf32_split(v.y * rp, hi, lo);
        ph[(kc * 4 + 1) * PPO + o] = hi;  pl[(kc * 4 + 1) * PPO + o] = lo;
        tf32_split(v.z * rp, hi, lo);
        ph[(kc * 4 + 2) * PPO + o] = hi;  pl[(kc * 4 + 2) * PPO + o] = lo;
        tf32_split(v.w * rp, hi, lo);
        ph[(kc * 4 + 3) * PPO + o] = hi;  pl[(kc * 4 + 3) * PPO + o] = lo;
    }
    __syncthreads();

    const int warp = tid >> 5;
    const int lane = tid & 31;
    const int g    = lane >> 2;          // groupID 0..7
    const int tg   = lane & 3;           // threadID_in_group 0..3
    const int ob   = warp * 16;          // warp's o offset within tile

    float d[2][2][4];
    #pragma unroll
    for (int mt = 0; mt < 2; mt++)
        #pragma unroll
        for (int nt = 0; nt < 2; nt++)
            #pragma unroll
            for (int r = 0; r < 4; r++) d[mt][nt][r] = 0.f;

    #pragma unroll
    for (int ks = 0; ks < KB / 8; ks++) {
        const int kb = ks * 8;

        // A fragments (hi and lo), 2 m-tiles
        uint32_t ah[2][4], al[2][4];
        #pragma unroll
        for (int mt = 0; mt < 2; mt++) {
            const int r0 = mt * 16 + g;
            ah[mt][0] = __float_as_uint(mh[(kb + tg) * PMB + r0]);
            ah[mt][1] = __float_as_uint(mh[(kb + tg) * PMB + r0 + 8]);
            ah[mt][2] = __float_as_uint(mh[(kb + tg + 4) * PMB + r0]);
            ah[mt][3] = __float_as_uint(mh[(kb + tg + 4) * PMB + r0 + 8]);
            al[mt][0] = __float_as_uint(ml[(kb + tg) * PMB + r0]);
            al[mt][1] = __float_as_uint(ml[(kb + tg) * PMB + r0 + 8]);
            al[mt][2] = __float_as_uint(ml[(kb + tg + 4) * PMB + r0]);
            al[mt][3] = __float_as_uint(ml[(kb + tg + 4) * PMB + r0 + 8]);
        }
        // B fragments (hi and lo), 2 n-tiles
        uint32_t bh[2][2], bl[2][2];
        #pragma unroll
        for (int nt = 0; nt < 2; nt++) {
            const int n0 = ob + nt * 8 + g;
            bh[nt][0] = __float_as_uint(ph[(kb + tg) * PPO + n0]);
            bh[nt][1] = __float_as_uint(ph[(kb + tg + 4) * PPO + n0]);
            bl[nt][0] = __float_as_uint(pl[(kb + tg) * PPO + n0]);
            bl[nt][1] = __float_as_uint(pl[(kb + tg + 4) * PPO + n0]);
        }

        #pragma unroll
        for (int mt = 0; mt < 2; mt++)
            #pragma unroll
            for (int nt = 0; nt < 2; nt++) {
                mma_tf32(d[mt][nt], ah[mt], bh[nt]);   // hi*hi
                mma_tf32(d[mt][nt], ah[mt], bl[nt]);   // hi*lo
                mma_tf32(d[mt][nt], al[mt], bh[nt]);   // lo*hi
            }
    }

    // epilogue: c0=[g][2tg], c1=[g][2tg+1], c2=[g+8][2tg], c3=[g+8][2tg+1]
    #pragma unroll
    for (int mt = 0; mt < 2; mt++) {
        #pragma unroll
        for (int nt = 0; nt < 2; nt++) {
            const int row = mt * 16 + g;
            const int col = ot * OTILE + ob + nt * 8 + 2 * tg;
            float* dst0 = out + (size_t)row * O_ + col;
            float* dst1 = out + (size_t)(row + 8) * O_ + col;
            asm volatile("red.global.add.v2.f32 [%0], {%1, %2};"
                         :: "l"(dst0), "f"(d[mt][nt][0]), "f"(d[mt][nt][1])
                         : "memory");
            asm volatile("red.global.add.v2.f32 [%0], {%1, %2};"
                         :: "l"(dst1), "f"(d[mt][nt][2]), "f"(d[mt][nt][3])
                         : "memory");
        }
    }
}

// ---------------------------------------------------------------------------
extern "C" void kernel_launch(void* const* d_in, const int* in_sizes, int n_in,
                              void* d_out, int out_size) {
    const float* x = (const float*)d_in[0];   // [32, 512, 768]
    const float* p = (const float*)d_in[1];   // [2048, 768]
    float*     out = (float*)d_out;           // [32, 2048]

    (void)in_sizes; (void)n_in; (void)out_size;

    reduce_x_kernel<<<128 + 16, 512>>>(x, p, out);
    gemm_kernel<<<NOT_ * KSPLIT, 256>>>(p, out);
}

// round 13
// speedup vs baseline: 1.1029x; 1.1029x over previous
#include <cuda_runtime.h>
#include <cuda_bf16.h>
#include <math.h>
#include <stdint.h>

// ---------------------------------------------------------------------------
// RandomProjection: out[b,o] = mean_s( cos(x[b,s,:], p[o,:]) )
//   kernel 1: m = mean_s(x/||x||) (ticket combine) + p-norms + zero(out)
//   kernel 2: bf16 3-term tensor-core GEMM (mma.m16n8k16 + ldmatrix.x4),
//             rpn folded into staged p, red.add.v2.f32 epilogue
// ---------------------------------------------------------------------------

#define B_     32
#define S_     512
#define D_     768
#define O_     2048
#define EPS_   1e-8f

#define KSPLIT 24
#define KB     32            // k floats per gemm block
#define OTILE  128           // o rows per gemm block
#define NOT_   (O_ / OTILE)  // 16 o-tiles
#define PA     56            // bf16 smem pitch: 112B rows, 16B-aligned, LDSM-conflict-free

__device__ float g_part[4 * B_ * D_];    // x partials (race-free)
__device__ float g_m[B_ * D_];           // combined mean (f32)
__device__ float g_rpn[O_];              // 1/max(||p_o||,eps)
__device__ int   g_ticket[B_];           // kernel1 tickets (zero-init, self-reset)

// ---------------------------------------------------------------------------
// Kernel 1 (R10 version): x reduce + ticket combine; p-norms + zero(out).
// ---------------------------------------------------------------------------
__global__ void __launch_bounds__(512, 1)
reduce_x_kernel(const float* __restrict__ x, const float* __restrict__ p,
                float* __restrict__ out) {
    const int warp = threadIdx.x >> 5;
    const int lane = threadIdx.x & 31;

    if (blockIdx.x >= 128) {
        const int blk = blockIdx.x - 128;      // 0..15
        {
            float4* o4 = reinterpret_cast<float4*>(out) + blk * 1024;
            o4[threadIdx.x]       = make_float4(0.f, 0.f, 0.f, 0.f);
            o4[threadIdx.x + 512] = make_float4(0.f, 0.f, 0.f, 0.f);
        }
        const int row0 = blk * 128 + warp * 8;
        #pragma unroll 1
        for (int r = 0; r < 8; r++) {
            const int o = row0 + r;
            const float4* prow = reinterpret_cast<const float4*>(p + (size_t)o * D_);
            float ss = 0.f;
            #pragma unroll
            for (int c = 0; c < 6; c++) {
                const float4 v = prow[lane + 32 * c];
                ss += v.x * v.x + v.y * v.y + v.z * v.z + v.w * v.w;
            }
            #pragma unroll
            for (int off = 16; off > 0; off >>= 1)
                ss += __shfl_xor_sync(0xFFFFFFFFu, ss, off);
            if (lane == 0) g_rpn[o] = 1.0f / fmaxf(sqrtf(ss), EPS_);
        }
        return;
    }

    __shared__ float4 sm[16 * 192];
    __shared__ int is_last;

    const int q = blockIdx.x & 3;
    const int b = blockIdx.x >> 2;

    const float4* base = reinterpret_cast<const float4*>(
        x + ((size_t)b * S_ + (size_t)q * 128 + (size_t)warp * 8) * D_);

    const float inv_S = 1.0f / (float)S_;

    float4 acc[6];
    #pragma unroll
    for (int c = 0; c < 6; c++) acc[c] = make_float4(0.f, 0.f, 0.f, 0.f);

    float4 v[6];
    #pragma unroll
    for (int c = 0; c < 6; c++) v[c] = base[lane + 32 * c];

    #pragma unroll
    for (int r = 0; r < 8; r++) {
        float4 vn[6];
        if (r < 7) {
            #pragma unroll
            for (int c = 0; c < 6; c++)
                vn[c] = base[(r + 1) * 192 + lane + 32 * c];
        }
        float ss = 0.f;
        #pragma unroll
        for (int c = 0; c < 6; c++)
            ss += v[c].x * v[c].x + v[c].y * v[c].y
                + v[c].z * v[c].z + v[c].w * v[c].w;
        #pragma unroll
        for (int off = 16; off > 0; off >>= 1)
            ss += __shfl_xor_sync(0xFFFFFFFFu, ss, off);

        const float scale = inv_S / fmaxf(sqrtf(ss), EPS_);
        #pragma unroll
        for (int c = 0; c < 6; c++) {
            acc[c].x += v[c].x * scale;
            acc[c].y += v[c].y * scale;
            acc[c].z += v[c].z * scale;
            acc[c].w += v[c].w * scale;
        }
        if (r < 7) {
            #pragma unroll
            for (int c = 0; c < 6; c++) v[c] = vn[c];
        }
    }

    #pragma unroll
    for (int c = 0; c < 6; c++)
        sm[warp * 192 + lane + 32 * c] = acc[c];
    __syncthreads();

    if (threadIdx.x < 192) {
        float4 s = sm[threadIdx.x];
        #pragma unroll
        for (int w = 1; w < 16; w++) {
            const float4 t = sm[w * 192 + threadIdx.x];
            s.x += t.x; s.y += t.y; s.z += t.z; s.w += t.w;
        }
        reinterpret_cast<float4*>(g_part)[((q * B_ + b) * 192) + threadIdx.x] = s;
    }

    __threadfence();
    __syncthreads();
    if (threadIdx.x == 0)
        is_last = (atomicAdd(&g_ticket[b], 1) == 3) ? 1 : 0;
    __syncthreads();

    if (is_last) {
        __threadfence();
        if (threadIdx.x < 192) {
            const float4* gp = reinterpret_cast<const float4*>(g_part);
            float4 a  = gp[(0 * B_ + b) * 192 + threadIdx.x];
            const float4 b4 = gp[(1 * B_ + b) * 192 + threadIdx.x];
            const float4 c4 = gp[(2 * B_ + b) * 192 + threadIdx.x];
            const float4 d4 = gp[(3 * B_ + b) * 192 + threadIdx.x];
            a.x += b4.x + c4.x + d4.x;
            a.y += b4.y + c4.y + d4.y;
            a.z += b4.z + c4.z + d4.z;
            a.w += b4.w + c4.w + d4.w;
            reinterpret_cast<float4*>(g_m)[b * 192 + threadIdx.x] = a;
        }
        if (threadIdx.x == 0) g_ticket[b] = 0;
    }
}

// ---- bf16 split helpers -----------------------------------------------------
__device__ __forceinline__ void bf16_split(float v, __nv_bfloat16& h, __nv_bfloat16& l) {
    h = __float2bfloat16(v);
    l = __float2bfloat16(v - __bfloat162float(h));
}
__device__ __forceinline__ uint32_t pack2(__nv_bfloat16 lo, __nv_bfloat16 hi) {
    const __nv_bfloat162 t = __halves2bfloat162(lo, hi);   // x=lo (low 16b)
    return *reinterpret_cast<const uint32_t*>(&t);
}

// ---- ldmatrix / mma ----------------------------------------------------------
__device__ __forceinline__ void ldsm_x4(uint32_t* r, uint32_t addr) {
    asm volatile("ldmatrix.sync.aligned.m8n8.x4.shared.b16 {%0,%1,%2,%3}, [%4];"
                 : "=r"(r[0]), "=r"(r[1]), "=r"(r[2]), "=r"(r[3]) : "r"(addr));
}
__device__ __forceinline__ void mma_bf16(float* d, const uint32_t* a,
                                         uint32_t b0, uint32_t b1) {
    asm volatile(
        "mma.sync.aligned.m16n8k16.row.col.f32.bf16.bf16.f32 "
        "{%0,%1,%2,%3}, {%4,%5,%6,%7}, {%8,%9}, {%0,%1,%2,%3};"
        : "+f"(d[0]), "+f"(d[1]), "+f"(d[2]), "+f"(d[3])
        : "r"(a[0]), "r"(a[1]), "r"(a[2]), "r"(a[3]), "r"(b0), "r"(b1));
}

// ---------------------------------------------------------------------------
// Kernel 2: bf16 3-term tensor GEMM.
// Grid: 384 = 16 o-tiles x 24 k-splits. Block: 256 threads (8 warps), 35 KB.
// Warp: M=32 (2 m16 tiles, full B), N=16 (warp*16 in o-tile), KB=32 (2 k16).
// Per k16 step per warp: 6 ldmatrix.x4 + 12 mma.m16n8k16 (hh, hl, lh terms).
// psm pre-scaled by rpn; epilogue = red.global.add.v2.f32.
// ---------------------------------------------------------------------------
__global__ void __launch_bounds__(256, 4)
gemm_kernel(const float* __restrict__ p, float* __restrict__ out) {
    __shared__ __align__(16) __nv_bfloat16 mh[B_ * PA];
    __shared__ __align__(16) __nv_bfloat16 ml[B_ * PA];
    __shared__ __align__(16) __nv_bfloat16 ph[OTILE * PA];
    __shared__ __align__(16) __nv_bfloat16 pl[OTILE * PA];

    const int kq  = blockIdx.x % KSPLIT;
    const int ot  = blockIdx.x / KSPLIT;    // 0..15
    const int tid = threadIdx.x;
    const int k0  = kq * KB;

    // stage m: 32 rows x 32 k -> hi/lo bf16, row-major [b][k]
    {
        const int b  = tid >> 3;             // 0..31
        const int kc = tid & 7;              // 0..7
        const float4 v = *reinterpret_cast<const float4*>(
            g_m + (size_t)b * D_ + k0 + kc * 4);
        __nv_bfloat16 h0, l0, h1, l1, h2, l2, h3, l3;
        bf16_split(v.x, h0, l0); bf16_split(v.y, h1, l1);
        bf16_split(v.z, h2, l2); bf16_split(v.w, h3, l3);
        *reinterpret_cast<uint2*>(mh + b * PA + kc * 4) =
            make_uint2(pack2(h0, h1), pack2(h2, h3));
        *reinterpret_cast<uint2*>(ml + b * PA + kc * 4) =
            make_uint2(pack2(l0, l1), pack2(l2, l3));
    }
    // stage p*rpn: 128 rows x 32 k -> hi/lo bf16, row-major [o][k]
    #pragma unroll
    for (int t2 = 0; t2 < 4; t2++) {
        const int i  = tid + t2 * 256;       // 0..1023
        const int o  = i >> 3;               // 0..127
        const int kc = i & 7;                // 0..7
        float4 v = *reinterpret_cast<const float4*>(
            p + (size_t)(ot * OTILE + o) * D_ + k0 + kc * 4);
        const float rp = g_rpn[ot * OTILE + o];
        v.x *= rp; v.y *= rp; v.z *= rp; v.w *= rp;
        __nv_bfloat16 h0, l0, h1, l1, h2, l2, h3, l3;
        bf16_split(v.x, h0, l0); bf16_split(v.y, h1, l1);
        bf16_split(v.z, h2, l2); bf16_split(v.w, h3, l3);
        *reinterpret_cast<uint2*>(ph + o * PA + kc * 4) =
            make_uint2(pack2(h0, h1), pack2(h2, h3));
        *reinterpret_cast<uint2*>(pl + o * PA + kc * 4) =
            make_uint2(pack2(l0, l1), pack2(l2, l3));
    }
    __syncthreads();

    const int warp = tid >> 5;
    const int lane = tid & 31;
    const int g    = lane >> 2;          // groupID 0..7
    const int tg   = lane & 3;           // threadID_in_group 0..3

    // ldmatrix per-lane row/k-segment assignment
    const int arow  = (lane & 7) + ((lane >> 3) & 1) * 8;   // + mt*16
    const int akseg = (lane >> 4) & 1;                      // * 8 elements
    const int brow  = warp * 16 + (lane & 7) + (lane >> 4) * 8;
    const int bkseg = (lane >> 3) & 1;

    const uint32_t mh_u = (uint32_t)__cvta_generic_to_shared(mh);
    const uint32_t ml_u = (uint32_t)__cvta_generic_to_shared(ml);
    const uint32_t ph_u = (uint32_t)__cvta_generic_to_shared(ph);
    const uint32_t pl_u = (uint32_t)__cvta_generic_to_shared(pl);

    float d[2][2][4];
    #pragma unroll
    for (int mt = 0; mt < 2; mt++)
        #pragma unroll
        for (int nt = 0; nt < 2; nt++)
            #pragma unroll
            for (int r = 0; r < 4; r++) d[mt][nt][r] = 0.f;

    #pragma unroll
    for (int ks = 0; ks < 2; ks++) {
        const int kb = ks * 16;

        uint32_t ah[2][4], al[2][4];
        #pragma unroll
        for (int mt = 0; mt < 2; mt++) {
            const uint32_t off =
                ((mt * 16 + arow) * PA + kb + akseg * 8) * 2;
            ldsm_x4(ah[mt], mh_u + off);
            ldsm_x4(al[mt], ml_u + off);
        }
        uint32_t bh[4], bl[4];   // [0]=nt0.b0 [1]=nt0.b1 [2]=nt1.b0 [3]=nt1.b1
        {
            const uint32_t off = (brow * PA + kb + bkseg * 8) * 2;
            ldsm_x4(bh, ph_u + off);
            ldsm_x4(bl, pl_u + off);
        }

        #pragma unroll
        for (int mt = 0; mt < 2; mt++)
            #pragma unroll
            for (int nt = 0; nt < 2; nt++) {
                mma_bf16(d[mt][nt], ah[mt], bh[2 * nt], bh[2 * nt + 1]); // hi*hi
                mma_bf16(d[mt][nt], ah[mt], bl[2 * nt], bl[2 * nt + 1]); // hi*lo
                mma_bf16(d[mt][nt], al[mt], bh[2 * nt], bh[2 * nt + 1]); // lo*hi
            }
    }

    // epilogue: c0,c1 = [g][2tg,2tg+1]; c2,c3 = [g+8][same]
    #pragma unroll
    for (int mt = 0; mt < 2; mt++) {
        #pragma unroll
        for (int nt = 0; nt < 2; nt++) {
            const int row = mt * 16 + g;
            const int col = ot * OTILE + warp * 16 + nt * 8 + 2 * tg;
            float* dst0 = out + (size_t)row * O_ + col;
            float* dst1 = out + (size_t)(row + 8) * O_ + col;
            asm volatile("red.global.add.v2.f32 [%0], {%1, %2};"
                         :: "l"(dst0), "f"(d[mt][nt][0]), "f"(d[mt][nt][1])
                         : "memory");
            asm volatile("red.global.add.v2.f32 [%0], {%1, %2};"
                         :: "l"(dst1), "f"(d[mt][nt][2]), "f"(d[mt][nt][3])
                         : "memory");
        }
    }
}

// ---------------------------------------------------------------------------
extern "C" void kernel_launch(void* const* d_in, const int* in_sizes, int n_in,
                              void* d_out, int out_size) {
    const float* x = (const float*)d_in[0];   // [32, 512, 768]
    const float* p = (const float*)d_in[1];   // [2048, 768]
    float*     out = (float*)d_out;           // [32, 2048]

    (void)in_sizes; (void)n_in; (void)out_size;

    reduce_x_kernel<<<128 + 16, 512>>>(x, p, out);
    gemm_kernel<<<NOT_ * KSPLIT, 256>>>(p, out);
}

// round 14
// speedup vs baseline: 1.2739x; 1.1550x over previous
#include <cuda_runtime.h>
#include <cuda_bf16.h>
#include <math.h>
#include <stdint.h>

// ---------------------------------------------------------------------------
// RandomProjection: out[b,o] = mean_s( cos(x[b,s,:], p[o,:]) )
//   kernel 1: blocks 0..127: x normalize+reduce -> 4 race-free partials
//             blocks 128..191: p-norms -> g_rpn, zero(out)
//             (no tickets, no fences — kernel boundary orders everything)
//   kernel 2: bf16 3-term tensor GEMM (m16n8k16 + ldmatrix.x4);
//             staging combines the 4 m-partials and folds rpn into p;
//             red.add.v2.f32 epilogue
// ---------------------------------------------------------------------------

#define B_     32
#define S_     512
#define D_     768
#define O_     2048
#define EPS_   1e-8f

#define KSPLIT 12
#define KB     64            // k floats per gemm block
#define OTILE  64            // o rows per gemm block
#define NOT_   (O_ / OTILE)  // 32 o-tiles
#define PA     72            // bf16 smem pitch (144B rows, LDSM conflict-free)

__device__ float g_part[4 * B_ * D_];    // x partials (race-free)
__device__ float g_rpn[O_];              // 1/max(||p_o||,eps)

// ---------------------------------------------------------------------------
// Kernel 1
// ---------------------------------------------------------------------------
__global__ void __launch_bounds__(512, 1)
reduce_x_kernel(const float* __restrict__ x, const float* __restrict__ p,
                float* __restrict__ out) {
    const int warp = threadIdx.x >> 5;
    const int lane = threadIdx.x & 31;

    if (blockIdx.x >= 128) {
        const int pb = blockIdx.x - 128;       // 0..63
        // zero out-slice: 16384 float4 / 64 blocks = 256 per block
        if (threadIdx.x < 256)
            reinterpret_cast<float4*>(out)[pb * 256 + threadIdx.x] =
                make_float4(0.f, 0.f, 0.f, 0.f);
        // p-norms: 32 rows per block, 2 per warp
        #pragma unroll
        for (int r = 0; r < 2; r++) {
            const int o = pb * 32 + warp * 2 + r;
            const float4* prow = reinterpret_cast<const float4*>(p + (size_t)o * D_);
            float ss = 0.f;
            #pragma unroll
            for (int c = 0; c < 6; c++) {
                const float4 v = prow[lane + 32 * c];
                ss += v.x * v.x + v.y * v.y + v.z * v.z + v.w * v.w;
            }
            #pragma unroll
            for (int off = 16; off > 0; off >>= 1)
                ss += __shfl_xor_sync(0xFFFFFFFFu, ss, off);
            if (lane == 0) g_rpn[o] = 1.0f / fmaxf(sqrtf(ss), EPS_);
        }
        return;
    }

    __shared__ float4 sm[16 * 192];

    const int q = blockIdx.x & 3;
    const int b = blockIdx.x >> 2;

    const float4* base = reinterpret_cast<const float4*>(
        x + ((size_t)b * S_ + (size_t)q * 128 + (size_t)warp * 8) * D_);

    const float inv_S = 1.0f / (float)S_;

    float4 acc[6];
    #pragma unroll
    for (int c = 0; c < 6; c++) acc[c] = make_float4(0.f, 0.f, 0.f, 0.f);

    float4 v[6];
    #pragma unroll
    for (int c = 0; c < 6; c++) v[c] = base[lane + 32 * c];

    #pragma unroll
    for (int r = 0; r < 8; r++) {
        float4 vn[6];
        if (r < 7) {
            #pragma unroll
            for (int c = 0; c < 6; c++)
                vn[c] = base[(r + 1) * 192 + lane + 32 * c];
        }
        float ss = 0.f;
        #pragma unroll
        for (int c = 0; c < 6; c++)
            ss += v[c].x * v[c].x + v[c].y * v[c].y
                + v[c].z * v[c].z + v[c].w * v[c].w;
        #pragma unroll
        for (int off = 16; off > 0; off >>= 1)
            ss += __shfl_xor_sync(0xFFFFFFFFu, ss, off);

        const float scale = inv_S / fmaxf(sqrtf(ss), EPS_);
        #pragma unroll
        for (int c = 0; c < 6; c++) {
            acc[c].x += v[c].x * scale;
            acc[c].y += v[c].y * scale;
            acc[c].z += v[c].z * scale;
            acc[c].w += v[c].w * scale;
        }
        if (r < 7) {
            #pragma unroll
            for (int c = 0; c < 6; c++) v[c] = vn[c];
        }
    }

    #pragma unroll
    for (int c = 0; c < 6; c++)
        sm[warp * 192 + lane + 32 * c] = acc[c];
    __syncthreads();

    if (threadIdx.x < 192) {
        float4 s = sm[threadIdx.x];
        #pragma unroll
        for (int w = 1; w < 16; w++) {
            const float4 t = sm[w * 192 + threadIdx.x];
            s.x += t.x; s.y += t.y; s.z += t.z; s.w += t.w;
        }
        reinterpret_cast<float4*>(g_part)[((q * B_ + b) * 192) + threadIdx.x] = s;
    }
}

// ---- bf16 split helpers -----------------------------------------------------
__device__ __forceinline__ void bf16_split(float v, __nv_bfloat16& h, __nv_bfloat16& l) {
    h = __float2bfloat16(v);
    l = __float2bfloat16(v - __bfloat162float(h));
}
__device__ __forceinline__ uint32_t pack2(__nv_bfloat16 lo, __nv_bfloat16 hi) {
    const __nv_bfloat162 t = __halves2bfloat162(lo, hi);   // x=lo (low 16b)
    return *reinterpret_cast<const uint32_t*>(&t);
}

// ---- ldmatrix / mma ----------------------------------------------------------
__device__ __forceinline__ void ldsm_x4(uint32_t* r, uint32_t addr) {
    asm volatile("ldmatrix.sync.aligned.m8n8.x4.shared.b16 {%0,%1,%2,%3}, [%4];"
                 : "=r"(r[0]), "=r"(r[1]), "=r"(r[2]), "=r"(r[3]) : "r"(addr));
}
__device__ __forceinline__ void mma_bf16(float* d, const uint32_t* a,
                                         uint32_t b0, uint32_t b1) {
    asm volatile(
        "mma.sync.aligned.m16n8k16.row.col.f32.bf16.bf16.f32 "
        "{%0,%1,%2,%3}, {%4,%5,%6,%7}, {%8,%9}, {%0,%1,%2,%3};"
        : "+f"(d[0]), "+f"(d[1]), "+f"(d[2]), "+f"(d[3])
        : "r"(a[0]), "r"(a[1]), "r"(a[2]), "r"(a[3]), "r"(b0), "r"(b1));
}

// ---------------------------------------------------------------------------
// Kernel 2: bf16 3-term tensor GEMM.
// Grid: 384 = 32 o-tiles x 12 k-splits. Block: 128 threads (4 warps), 27 KB.
// Warp: M=32 (2 m16 tiles, full B), N=16 (warp*16 in 64-o tile), KB=64.
// Staging combines 4 m-partials + splits to bf16 hi/lo; p scaled by rpn.
// Per k16 step per warp: 6 ldmatrix.x4 + 12 mma (hh, hl, lh).
// ---------------------------------------------------------------------------
__global__ void __launch_bounds__(128, 8)
gemm_kernel(const float* __restrict__ p, float* __restrict__ out) {
    __shared__ __align__(16) __nv_bfloat16 mh[B_ * PA];
    __shared__ __align__(16) __nv_bfloat16 ml[B_ * PA];
    __shared__ __align__(16) __nv_bfloat16 ph[OTILE * PA];
    __shared__ __align__(16) __nv_bfloat16 pl[OTILE * PA];

    const int kq  = blockIdx.x % KSPLIT;
    const int ot  = blockIdx.x / KSPLIT;    // 0..31
    const int tid = threadIdx.x;
    const int k0  = kq * KB;

    // stage m: combine 4 partials, split -> hi/lo bf16, [b][k] row-major
    // 32 rows x 16 float4 = 512 positions, 4 per thread
    {
        const float4* gp = reinterpret_cast<const float4*>(g_part);
        #pragma unroll
        for (int t = 0; t < 4; t++) {
            const int i  = tid + t * 128;    // 0..511
            const int b  = i >> 4;           // 0..31
            const int kc = i & 15;           // 0..15
            const int col = kq * 16 + kc;
            float4 s = gp[(0 * B_ + b) * 192 + col];
            #pragma unroll
            for (int e = 1; e < 4; e++) {
                const float4 t4 = gp[(e * B_ + b) * 192 + col];
                s.x += t4.x; s.y += t4.y; s.z += t4.z; s.w += t4.w;
            }
            __nv_bfloat16 h0, l0, h1, l1, h2, l2, h3, l3;
            bf16_split(s.x, h0, l0); bf16_split(s.y, h1, l1);
            bf16_split(s.z, h2, l2); bf16_split(s.w, h3, l3);
            *reinterpret_cast<uint2*>(mh + b * PA + kc * 4) =
                make_uint2(pack2(h0, h1), pack2(h2, h3));
            *reinterpret_cast<uint2*>(ml + b * PA + kc * 4) =
                make_uint2(pack2(l0, l1), pack2(l2, l3));
        }
    }
    // stage p*rpn: 64 rows x 16 float4 = 1024 positions, 8 per thread
    #pragma unroll
    for (int t = 0; t < 8; t++) {
        const int i  = tid + t * 128;        // 0..1023
        const int o  = i >> 4;               // 0..63
        const int kc = i & 15;               // 0..15
        float4 v = *reinterpret_cast<const float4*>(
            p + (size_t)(ot * OTILE + o) * D_ + k0 + kc * 4);
        const float rp = g_rpn[ot * OTILE + o];
        v.x *= rp; v.y *= rp; v.z *= rp; v.w *= rp;
        __nv_bfloat16 h0, l0, h1, l1, h2, l2, h3, l3;
        bf16_split(v.x, h0, l0); bf16_split(v.y, h1, l1);
        bf16_split(v.z, h2, l2); bf16_split(v.w, h3, l3);
        *reinterpret_cast<uint2*>(ph + o * PA + kc * 4) =
            make_uint2(pack2(h0, h1), pack2(h2, h3));
        *reinterpret_cast<uint2*>(pl + o * PA + kc * 4) =
            make_uint2(pack2(l0, l1), pack2(l2, l3));
    }
    __syncthreads();

    const int warp = tid >> 5;
    const int lane = tid & 31;
    const int g    = lane >> 2;          // groupID 0..7
    const int tg   = lane & 3;           // threadID_in_group 0..3

    const int arow  = (lane & 7) + ((lane >> 3) & 1) * 8;   // + mt*16
    const int akseg = (lane >> 4) & 1;                      // * 8 elements
    const int brow  = warp * 16 + (lane & 7) + (lane >> 4) * 8;
    const int bkseg = (lane >> 3) & 1;

    const uint32_t mh_u = (uint32_t)__cvta_generic_to_shared(mh);
    const uint32_t ml_u = (uint32_t)__cvta_generic_to_shared(ml);
    const uint32_t ph_u = (uint32_t)__cvta_generic_to_shared(ph);
    const uint32_t pl_u = (uint32_t)__cvta_generic_to_shared(pl);

    float d[2][2][4];
    #pragma unroll
    for (int mt = 0; mt < 2; mt++)
        #pragma unroll
        for (int nt = 0; nt < 2; nt++)
            #pragma unroll
            for (int r = 0; r < 4; r++) d[mt][nt][r] = 0.f;

    #pragma unroll
    for (int ks = 0; ks < KB / 16; ks++) {
        const int kb = ks * 16;

        uint32_t ah[2][4], al[2][4];
        #pragma unroll
        for (int mt = 0; mt < 2; mt++) {
            const uint32_t off = ((mt * 16 + arow) * PA + kb + akseg * 8) * 2;
            ldsm_x4(ah[mt], mh_u + off);
            ldsm_x4(al[mt], ml_u + off);
        }
        uint32_t bh[4], bl[4];
        {
            const uint32_t off = (brow * PA + kb + bkseg * 8) * 2;
            ldsm_x4(bh, ph_u + off);
            ldsm_x4(bl, pl_u + off);
        }

        #pragma unroll
        for (int mt = 0; mt < 2; mt++)
            #pragma unroll
            for (int nt = 0; nt < 2; nt++) {
                mma_bf16(d[mt][nt], ah[mt], bh[2 * nt], bh[2 * nt + 1]); // hi*hi
                mma_bf16(d[mt][nt], ah[mt], bl[2 * nt], bl[2 * nt + 1]); // hi*lo
                mma_bf16(d[mt][nt], al[mt], bh[2 * nt], bh[2 * nt + 1]); // lo*hi
            }
    }

    // epilogue
    #pragma unroll
    for (int mt = 0; mt < 2; mt++) {
        #pragma unroll
        for (int nt = 0; nt < 2; nt++) {
            const int row = mt * 16 + g;
            const int col = ot * OTILE + warp * 16 + nt * 8 + 2 * tg;
            float* dst0 = out + (size_t)row * O_ + col;
            float* dst1 = out + (size_t)(row + 8) * O_ + col;
            asm volatile("red.global.add.v2.f32 [%0], {%1, %2};"
                         :: "l"(dst0), "f"(d[mt][nt][0]), "f"(d[mt][nt][1])
                         : "memory");
            asm volatile("red.global.add.v2.f32 [%0], {%1, %2};"
                         :: "l"(dst1), "f"(d[mt][nt][2]), "f"(d[mt][nt][3])
                         : "memory");
        }
    }
}

// ---------------------------------------------------------------------------
extern "C" void kernel_launch(void* const* d_in, const int* in_sizes, int n_in,
                              void* d_out, int out_size) {
    const float* x = (const float*)d_in[0];   // [32, 512, 768]
    const float* p = (const float*)d_in[1];   // [2048, 768]
    float*     out = (float*)d_out;           // [32, 2048]

    (void)in_sizes; (void)n_in; (void)out_size;

    reduce_x_kernel<<<128 + 64, 512>>>(x, p, out);
    gemm_kernel<<<NOT_ * KSPLIT, 128>>>(p, out);
}